// round 3
// baseline (speedup 1.0000x reference)
#include <cuda_runtime.h>
#include <math.h>

// Problem constants
#define SQ    2048      // sequence length
#define HID   2048      // hidden
#define NHEAD 16
#define HDIM  128
#define MR    4096      // B*S rows

typedef unsigned long long ull;

// ---------------- scratch (static device arrays; no allocation allowed) ----------
__device__ float g_q [MR * HID];
__device__ float g_k [MR * HID];
__device__ float g_v [MR * HID];
__device__ float g_ao[MR * HID];
__device__ float g_bm[SQ];
__device__ float g_attn[134217728];   // 2*16*2048*2048 fallback if attn not in d_out

// ---------------- f32x2 helpers (Blackwell packed fp32 FMA) ----------------------
__device__ __forceinline__ ull dup2(float a) {
    ull r; asm("mov.b64 %0, {%1, %1};" : "=l"(r) : "f"(a)); return r;
}
__device__ __forceinline__ void fma2(ull& d, ull a, ull b) {
    asm("fma.rn.f32x2 %0, %1, %2, %0;" : "+l"(d) : "l"(a), "l"(b));
}
__device__ __forceinline__ float2 unpk(ull v) {
    float lo, hi; asm("mov.b64 {%0, %1}, %2;" : "=f"(lo), "=f"(hi) : "l"(v));
    return make_float2(lo, hi);
}

// =================================================================================
// NT GEMM: C[m,n] = scale * sum_k A[m,k] * B[n,k]
// 128x128 tile, BK=16, 256 threads, 8x8 per thread with f32x2 accumulators.
// Batched via blockIdx.z with (outer, inner) stride decomposition.
// causal!=0: skip tiles entirely above the diagonal (scores GEMM).
// =================================================================================
__global__ void __launch_bounds__(256, 2) gemm_nt_kernel(
    const float* __restrict__ A, const float* __restrict__ B, float* __restrict__ C,
    int K, int lda, int ldb, int ldc,
    long long aSb, long long aSh, long long bSb, long long bSh,
    long long cSb, long long cSh, int nInner, float scale, int causal)
{
    int z  = blockIdx.z;
    int bb = z / nInner, hh = z - bb * nInner;
    A += bb * aSb + hh * aSh;
    B += bb * bSb + hh * bSh;
    C += bb * cSb + hh * cSh;

    const int rowBase = blockIdx.y * 128;
    const int colBase = blockIdx.x * 128;
    if (causal && colBase > rowBase + 127) return;   // fully-masked tile

    __shared__ float As[16][132];
    __shared__ float Bs[16][132];

    const int tid = threadIdx.x;
    const int tx = tid & 15, ty = tid >> 4;

    ull acc[8][4];
#pragma unroll
    for (int i = 0; i < 8; i++)
#pragma unroll
        for (int j = 0; j < 4; j++) acc[i][j] = 0ull;

    for (int k0 = 0; k0 < K; k0 += 16) {
#pragma unroll
        for (int i = 0; i < 2; i++) {
            int j  = tid + i * 256;         // float4 id, 512 per tile
            int r  = j >> 2;                // 0..127
            int c4 = j & 3;                 // 0..3
            float4 av = *reinterpret_cast<const float4*>(
                A + (size_t)(rowBase + r) * lda + k0 + c4 * 4);
            As[c4*4+0][r] = av.x; As[c4*4+1][r] = av.y;
            As[c4*4+2][r] = av.z; As[c4*4+3][r] = av.w;
            float4 bv = *reinterpret_cast<const float4*>(
                B + (size_t)(colBase + r) * ldb + k0 + c4 * 4);
            Bs[c4*4+0][r] = bv.x; Bs[c4*4+1][r] = bv.y;
            Bs[c4*4+2][r] = bv.z; Bs[c4*4+3][r] = bv.w;
        }
        __syncthreads();
#pragma unroll
        for (int kk = 0; kk < 16; kk++) {
            float4 a0 = *reinterpret_cast<const float4*>(&As[kk][ty * 8]);
            float4 a1 = *reinterpret_cast<const float4*>(&As[kk][ty * 8 + 4]);
            const ull* bp = reinterpret_cast<const ull*>(&Bs[kk][tx * 8]);
            ull b0 = bp[0], b1 = bp[1], b2 = bp[2], b3 = bp[3];
            ull ad[8];
            ad[0] = dup2(a0.x); ad[1] = dup2(a0.y); ad[2] = dup2(a0.z); ad[3] = dup2(a0.w);
            ad[4] = dup2(a1.x); ad[5] = dup2(a1.y); ad[6] = dup2(a1.z); ad[7] = dup2(a1.w);
#pragma unroll
            for (int i = 0; i < 8; i++) {
                fma2(acc[i][0], ad[i], b0);
                fma2(acc[i][1], ad[i], b1);
                fma2(acc[i][2], ad[i], b2);
                fma2(acc[i][3], ad[i], b3);
            }
        }
        __syncthreads();
    }

#pragma unroll
    for (int i = 0; i < 8; i++) {
        float* crow = C + (size_t)(rowBase + ty * 8 + i) * ldc + colBase + tx * 8;
        float2 p0 = unpk(acc[i][0]), p1 = unpk(acc[i][1]);
        float2 p2 = unpk(acc[i][2]), p3 = unpk(acc[i][3]);
        float4 o0 = make_float4(p0.x * scale, p0.y * scale, p1.x * scale, p1.y * scale);
        float4 o1 = make_float4(p2.x * scale, p2.y * scale, p3.x * scale, p3.y * scale);
        *reinterpret_cast<float4*>(crow)     = o0;
        *reinterpret_cast<float4*>(crow + 4) = o1;
    }
}

// =================================================================================
// NN GEMM: C[m,n] = scale * sum_k A[m,k] * B[k,n]   (B is K-major rows, n contiguous)
// Used for attn @ v.
// =================================================================================
__global__ void __launch_bounds__(256, 2) gemm_nn_kernel(
    const float* __restrict__ A, const float* __restrict__ B, float* __restrict__ C,
    int K, int lda, int ldb, int ldc,
    long long aSb, long long aSh, long long bSb, long long bSh,
    long long cSb, long long cSh, int nInner, float scale)
{
    int z  = blockIdx.z;
    int bb = z / nInner, hh = z - bb * nInner;
    A += bb * aSb + hh * aSh;
    B += bb * bSb + hh * bSh;
    C += bb * cSb + hh * cSh;

    const int rowBase = blockIdx.y * 128;
    const int colBase = blockIdx.x * 128;

    __shared__ float As[16][132];
    __shared__ float Bs[16][132];

    const int tid = threadIdx.x;
    const int tx = tid & 15, ty = tid >> 4;

    ull acc[8][4];
#pragma unroll
    for (int i = 0; i < 8; i++)
#pragma unroll
        for (int j = 0; j < 4; j++) acc[i][j] = 0ull;

    for (int k0 = 0; k0 < K; k0 += 16) {
#pragma unroll
        for (int i = 0; i < 2; i++) {
            int j  = tid + i * 256;
            {   // A tile (K-contiguous rows) -> transposed into As[k][m]
                int r = j >> 2, c4 = j & 3;
                float4 av = *reinterpret_cast<const float4*>(
                    A + (size_t)(rowBase + r) * lda + k0 + c4 * 4);
                As[c4*4+0][r] = av.x; As[c4*4+1][r] = av.y;
                As[c4*4+2][r] = av.z; As[c4*4+3][r] = av.w;
            }
            {   // B tile [BK][BN], rows are k, n contiguous -> direct copy
                int r = j >> 5, c4 = j & 31;
                float4 bv = *reinterpret_cast<const float4*>(
                    B + (size_t)(k0 + r) * ldb + colBase + c4 * 4);
                *reinterpret_cast<float4*>(&Bs[r][c4 * 4]) = bv;
            }
        }
        __syncthreads();
#pragma unroll
        for (int kk = 0; kk < 16; kk++) {
            float4 a0 = *reinterpret_cast<const float4*>(&As[kk][ty * 8]);
            float4 a1 = *reinterpret_cast<const float4*>(&As[kk][ty * 8 + 4]);
            const ull* bp = reinterpret_cast<const ull*>(&Bs[kk][tx * 8]);
            ull b0 = bp[0], b1 = bp[1], b2 = bp[2], b3 = bp[3];
            ull ad[8];
            ad[0] = dup2(a0.x); ad[1] = dup2(a0.y); ad[2] = dup2(a0.z); ad[3] = dup2(a0.w);
            ad[4] = dup2(a1.x); ad[5] = dup2(a1.y); ad[6] = dup2(a1.z); ad[7] = dup2(a1.w);
#pragma unroll
            for (int i = 0; i < 8; i++) {
                fma2(acc[i][0], ad[i], b0);
                fma2(acc[i][1], ad[i], b1);
                fma2(acc[i][2], ad[i], b2);
                fma2(acc[i][3], ad[i], b3);
            }
        }
        __syncthreads();
    }

#pragma unroll
    for (int i = 0; i < 8; i++) {
        float* crow = C + (size_t)(rowBase + ty * 8 + i) * ldc + colBase + tx * 8;
        float2 p0 = unpk(acc[i][0]), p1 = unpk(acc[i][1]);
        float2 p2 = unpk(acc[i][2]), p3 = unpk(acc[i][3]);
        float4 o0 = make_float4(p0.x * scale, p0.y * scale, p1.x * scale, p1.y * scale);
        float4 o1 = make_float4(p2.x * scale, p2.y * scale, p3.x * scale, p3.y * scale);
        *reinterpret_cast<float4*>(crow)     = o0;
        *reinterpret_cast<float4*>(crow + 4) = o1;
    }
}

// =================================================================================
// bmean[s] = 0.1 * mean_k bias[s,k]
// =================================================================================
__global__ void bmean_kernel(const float* __restrict__ bias, float* __restrict__ bm)
{
    __shared__ float red[256];
    int r = blockIdx.x;
    const float* row = bias + (size_t)r * SQ;
    float s = 0.f;
    for (int i = threadIdx.x; i < SQ; i += 256) s += row[i];
    red[threadIdx.x] = s; __syncthreads();
    for (int off = 128; off; off >>= 1) {
        if (threadIdx.x < off) red[threadIdx.x] += red[threadIdx.x + off];
        __syncthreads();
    }
    if (threadIdx.x == 0) bm[r] = red[0] * (0.1f / 2048.0f);
}

// =================================================================================
// In-place RoPE on q and k + add bmean. One thread per (m, h, d2) pair, d2 in [0,64).
// =================================================================================
__global__ void rope_kernel(float* __restrict__ q, float* __restrict__ k,
                            const float* __restrict__ bm)
{
    int idx = blockIdx.x * 256 + threadIdx.x;      // < 4096*16*64 = 4194304
    int d2 = idx & 63;
    int h  = (idx >> 6) & 15;
    int m  = idx >> 10;                            // 0..4095  (b*S + s)
    int s  = m & (SQ - 1);

    float invf = (float)exp(-((double)(2 * d2) / 128.0) * log(10000.0));
    float ang  = (float)s * invf;                  // fp32 multiply like the reference
    float sn, cs;
    sincosf(ang, &sn, &cs);
    float b = bm[s];

    size_t off = (size_t)m * HID + (size_t)h * HDIM + d2;
    float q0 = q[off], q1 = q[off + 64];
    q[off]      = q0 * cs - q1 * sn + b;
    q[off + 64] = q1 * cs + q0 * sn + b;
    float k0 = k[off], k1 = k[off + 64];
    k[off]      = k0 * cs - k1 * sn + b;
    k[off + 64] = k1 * cs + k0 * sn + b;
}

// =================================================================================
// Row softmax with bias add + causal mask, in-place on the scores buffer.
// One block per (z, q) row. Only k<=q are live; k>q written as 0.
// =================================================================================
__global__ void softmax_kernel(float* __restrict__ attn, const float* __restrict__ bias)
{
    __shared__ float buf[2048];
    __shared__ float red[256];
    int qrow = blockIdx.x;
    long long base = (long long)blockIdx.y * SQ * SQ + (long long)qrow * SQ;
    float* row = attn + base;
    const float* brow = bias + (size_t)qrow * SQ;
    int L = qrow + 1;
    int tid = threadIdx.x;

    float mx = -3.402823466e38f;
    for (int i = tid; i < L; i += 256) {
        float v = row[i] + brow[i];
        buf[i] = v;
        mx = fmaxf(mx, v);
    }
    red[tid] = mx; __syncthreads();
    for (int off = 128; off; off >>= 1) {
        if (tid < off) red[tid] = fmaxf(red[tid], red[tid + off]);
        __syncthreads();
    }
    mx = red[0]; __syncthreads();

    float sum = 0.f;
    for (int i = tid; i < L; i += 256) {
        float e = __expf(buf[i] - mx);
        buf[i] = e;
        sum += e;
    }
    red[tid] = sum; __syncthreads();
    for (int off = 128; off; off >>= 1) {
        if (tid < off) red[tid] += red[tid + off];
        __syncthreads();
    }
    float inv = 1.0f / red[0];

    for (int i = tid; i < L; i += 256)       row[i] = buf[i] * inv;
    for (int i = L + tid; i < SQ; i += 256)  row[i] = 0.f;
}

// =================================================================================
// Host launcher
// =================================================================================
extern "C" void kernel_launch(void* const* d_in, const int* in_sizes, int n_in,
                              void* d_out, int out_size)
{
    const float* x    = (const float*)d_in[0];
    const float* Wq   = (const float*)d_in[1];
    const float* Wk   = (const float*)d_in[2];
    const float* Wv   = (const float*)d_in[3];
    const float* Wo   = (const float*)d_in[4];
    const float* bias = (const float*)d_in[5];
    float* out = (float*)d_out;

    float *pq, *pk, *pv, *pao, *pbm, *pattn;
    cudaGetSymbolAddress((void**)&pq,    g_q);
    cudaGetSymbolAddress((void**)&pk,    g_k);
    cudaGetSymbolAddress((void**)&pv,    g_v);
    cudaGetSymbolAddress((void**)&pao,   g_ao);
    cudaGetSymbolAddress((void**)&pbm,   g_bm);
    cudaGetSymbolAddress((void**)&pattn, g_attn);

    const long long OUT_N = 8388608LL;       // 2*2048*2048
    const long long ATT_N = 134217728LL;     // 2*16*2048*2048
    float* outPtr  = out;
    float* attnPtr;
    long long osz = (long long)out_size;
    if (osz >= OUT_N + ATT_N)      { attnPtr = out + OUT_N; }           // (output, attn)
    else if (osz == ATT_N)         { attnPtr = out; outPtr = pq; }      // attn only
    else                           { attnPtr = pattn; }                 // output only

    const long long SH = (long long)SQ * HID;   // 4194304
    const long long SS = (long long)SQ * SQ;    // 4194304

    // 1) per-row bias mean
    bmean_kernel<<<SQ, 256>>>(bias, pbm);

    // 2) QKV projections: y = x @ W^T   (M=4096, N=2048, K=2048)
    dim3 gProj(16, 32, 1);
    gemm_nt_kernel<<<gProj, 256>>>(x, Wq, pq, 2048, 2048, 2048, 2048,
                                   0, 0, 0, 0, 0, 0, 1, 1.0f, 0);
    gemm_nt_kernel<<<gProj, 256>>>(x, Wk, pk, 2048, 2048, 2048, 2048,
                                   0, 0, 0, 0, 0, 0, 1, 1.0f, 0);
    gemm_nt_kernel<<<gProj, 256>>>(x, Wv, pv, 2048, 2048, 2048, 2048,
                                   0, 0, 0, 0, 0, 0, 1, 1.0f, 0);

    // 3) RoPE + bmean on q, k (in place)
    rope_kernel<<<16384, 256>>>(pq, pk, pbm);

    // 4) scores = q.k^T / sqrt(D)   batched over z = b*16+h, causal tile-skip
    dim3 gScore(16, 16, 32);
    gemm_nt_kernel<<<gScore, 256>>>(pq, pk, attnPtr, 128, 2048, 2048, 2048,
                                    SH, 128, SH, 128,
                                    (long long)NHEAD * SS, SS,
                                    NHEAD, 0.08838834764831845f, 1);

    // 5) bias add + causal softmax (in place)
    softmax_kernel<<<dim3(SQ, 32), 256>>>(attnPtr, bias);

    // 6) attn @ v   (M=2048, N=128, K=2048) batched
    dim3 gAV(1, 16, 32);
    gemm_nn_kernel<<<gAV, 256>>>(attnPtr, pv, pao, 2048, 2048, 2048, 2048,
                                 (long long)NHEAD * SS, SS,
                                 SH, 128,
                                 SH, 128,
                                 NHEAD, 1.0f);

    // 7) output = attn_out @ Wo^T
    gemm_nt_kernel<<<gProj, 256>>>(pao, Wo, outPtr, 2048, 2048, 2048, 2048,
                                   0, 0, 0, 0, 0, 0, 1, 1.0f, 0);
}